// round 5
// baseline (speedup 1.0000x reference)
#include <cuda_runtime.h>
#include <cstdint>
#include <math.h>

#define BATCH   4
#define NNODES  4096
#define DIM     64

#define TM      64                    // M rows per CTA
#define KT      32                    // K per tile
#define NT      (NNODES / KT)         // 128 k-tiles
#define THREADS 128                   // 4 warps, warp tile 32x32 (warpgrid 2x2)

// ---------------- scratch ----------------
__device__ float g_deg[BATCH * NNODES];
__device__ float g_zA [BATCH * NNODES * DIM];
__device__ float g_zB [BATCH * NNODES * DIM];
__device__ float g_h1 [BATCH * NNODES * DIM];
__device__ float g_h2 [BATCH * NNODES * DIM];
__device__ float g_h3 [BATCH * NNODES * DIM];

// ---------------- helpers ----------------
__device__ __forceinline__ void cp_async16(void* smem_dst, const void* gmem_src) {
    unsigned s = (unsigned)__cvta_generic_to_shared(smem_dst);
    asm volatile("cp.async.cg.shared.global [%0], [%1], 16;\n" :: "r"(s), "l"(gmem_src));
}
__device__ __forceinline__ void cp_commit() {
    asm volatile("cp.async.commit_group;\n");
}
template<int NREM>
__device__ __forceinline__ void cp_wait() {
    asm volatile("cp.async.wait_group %0;\n" :: "n"(NREM));
}
__device__ __forceinline__ uint32_t f2tf32(float a) {
    uint32_t r; asm("cvt.rna.tf32.f32 %0, %1;" : "=r"(r) : "f"(a)); return r;
}
__device__ __forceinline__ void mma_tf32(float* c, const uint32_t* a, const uint32_t* b) {
    asm volatile(
        "mma.sync.aligned.m16n8k8.row.col.f32.tf32.tf32.f32 "
        "{%0,%1,%2,%3}, {%4,%5,%6,%7}, {%8,%9}, {%0,%1,%2,%3};"
        : "+f"(c[0]), "+f"(c[1]), "+f"(c[2]), "+f"(c[3])
        : "r"(a[0]), "r"(a[1]), "r"(a[2]), "r"(a[3]), "r"(b[0]), "r"(b[1]));
}

// ---------------- 1) degrees: d[b,i] = 1/(sqrt(1 + rowsum)+1e-7) ----------------
__global__ void degree_kernel(const float* __restrict__ graph, float* __restrict__ dvec) {
    const int row = blockIdx.x;
    const float4* g4 = (const float4*)(graph + (size_t)row * NNODES);
    float s = 0.f;
    #pragma unroll
    for (int k = 0; k < NNODES / 4 / 256; k++) {
        float4 v = g4[threadIdx.x + k * 256];
        s += (v.x + v.y) + (v.z + v.w);
    }
    #pragma unroll
    for (int o = 16; o > 0; o >>= 1) s += __shfl_down_sync(0xffffffffu, s, o);
    __shared__ float red[8];
    if ((threadIdx.x & 31) == 0) red[threadIdx.x >> 5] = s;
    __syncthreads();
    if (threadIdx.x == 0) {
        float tot = 1.0f;
        #pragma unroll
        for (int w = 0; w < 8; w++) tot += red[w];
        dvec[row] = 1.0f / (sqrtf(tot) + 1e-7f);
    }
}

// ---------------- 2) z0 = D * x ----------------
__global__ void scale_x_kernel(const float* __restrict__ x, const float* __restrict__ dvec,
                               float* __restrict__ z) {
    int idx = blockIdx.x * blockDim.x + threadIdx.x;
    float4 v = ((const float4*)x)[idx];
    float d = dvec[idx >> 4];
    v.x *= d; v.y *= d; v.z *= d; v.w *= d;
    ((float4*)z)[idx] = v;
}

// ---------------- 3) propagation GEMM via SIMT tensor-core mma (tf32 3-term split) ----
// acc = graph @ z ; h = d_i*(acc + z_i) ; z_out = d_i*h
__global__ void __launch_bounds__(THREADS)
prop_mma_kernel(const float* __restrict__ graph, const float* __restrict__ z_in,
                float* __restrict__ h_out, float* __restrict__ z_out)
{
    // A in fragment-friendly layout [kc][m][kr]  (kc = k>>2, kr = k&3): LDS conflict-free
    __shared__ float As[2][8][TM][4];       // 8 KB per stage
    __shared__ float Bs[2][KT][68];         // [k][n] padded to 68: ~2-way max

    const int tid  = threadIdx.x;
    const int lane = tid & 31;
    const int wid  = tid >> 5;
    const int wm   = (wid >> 1) * 32;       // warp M offset (0/32)
    const int wn   = (wid & 1) * 32;        // warp N offset (0/32)

    const int b = blockIdx.y;
    const int rowBase = blockIdx.x * TM;
    const float* G = graph + (size_t)b * NNODES * NNODES;
    const float* Z = z_in  + (size_t)b * NNODES * DIM;

    float acc[2][4][4];
    #pragma unroll
    for (int i = 0; i < 2; i++)
        #pragma unroll
        for (int j = 0; j < 4; j++)
            #pragma unroll
            for (int r = 0; r < 4; r++) acc[i][j][r] = 0.f;

    auto issue = [&](int t, int st) {
        const int k0 = t * KT;
        #pragma unroll
        for (int u = 0; u < 4; u++) {
            int idx = tid + u * THREADS;         // 0..511 16B chunks of A
            int kc = idx & 7, m = idx >> 3;
            cp_async16(&As[st][kc][m][0],
                       G + (size_t)(rowBase + m) * NNODES + k0 + kc * 4);
        }
        #pragma unroll
        for (int u = 0; u < 4; u++) {
            int idx = tid + u * THREADS;         // 0..511 16B chunks of B
            int n4 = idx & 15, k = idx >> 4;
            cp_async16(&Bs[st][k][n4 * 4],
                       Z + (size_t)(k0 + k) * DIM + n4 * 4);
        }
        cp_commit();
    };

    issue(0, 0);
    issue(1, 1);

    const int r0l = lane >> 2;      // 0..7
    const int krl = lane & 3;       // 0..3

    for (int t = 0; t < NT; t++) {
        const int st = t & 1;
        if (t + 1 < NT) cp_wait<1>(); else cp_wait<0>();
        __syncthreads();

        #pragma unroll
        for (int ks = 0; ks < 4; ks++) {
            // ---- A fragments (2 m-blocks), convert to tf32 hi/lo ----
            uint32_t ahi[2][4], alo[2][4];
            #pragma unroll
            for (int mb = 0; mb < 2; mb++) {
                const int r0 = wm + mb * 16 + r0l;
                const int r1 = r0 + 8;
                const int kc0 = ks * 2, kc1 = ks * 2 + 1;
                float f0 = As[st][kc0][r0][krl];
                float f1 = As[st][kc0][r1][krl];
                float f2 = As[st][kc1][r0][krl];
                float f3 = As[st][kc1][r1][krl];
                ahi[mb][0] = f2tf32(f0); alo[mb][0] = f2tf32(f0 - __uint_as_float(ahi[mb][0]));
                ahi[mb][1] = f2tf32(f1); alo[mb][1] = f2tf32(f1 - __uint_as_float(ahi[mb][1]));
                ahi[mb][2] = f2tf32(f2); alo[mb][2] = f2tf32(f2 - __uint_as_float(ahi[mb][2]));
                ahi[mb][3] = f2tf32(f3); alo[mb][3] = f2tf32(f3 - __uint_as_float(ahi[mb][3]));
            }
            // ---- B fragments (4 n-blocks), convert to tf32 hi/lo ----
            uint32_t bhi[4][2], blo[4][2];
            #pragma unroll
            for (int nb = 0; nb < 4; nb++) {
                const int n  = wn + nb * 8 + r0l;
                const int k0i = ks * 8 + krl;
                float g0 = Bs[st][k0i][n];
                float g1 = Bs[st][k0i + 4][n];
                bhi[nb][0] = f2tf32(g0); blo[nb][0] = f2tf32(g0 - __uint_as_float(bhi[nb][0]));
                bhi[nb][1] = f2tf32(g1); blo[nb][1] = f2tf32(g1 - __uint_as_float(bhi[nb][1]));
            }
            // ---- 3-term MMAs ----
            #pragma unroll
            for (int mb = 0; mb < 2; mb++)
                #pragma unroll
                for (int nb = 0; nb < 4; nb++) {
                    mma_tf32(acc[mb][nb], ahi[mb], bhi[nb]);
                    mma_tf32(acc[mb][nb], ahi[mb], blo[nb]);
                    mma_tf32(acc[mb][nb], alo[mb], bhi[nb]);
                }
        }
        __syncthreads();
        if (t + 2 < NT) issue(t + 2, st);
    }

    // ---- epilogue: h = d*(acc + z), z_out = d*h ----
    const float* D = g_deg + (size_t)b * NNODES;
    float* H  = h_out + (size_t)b * NNODES * DIM;
    float* ZO = z_out + (size_t)b * NNODES * DIM;
    #pragma unroll
    for (int mb = 0; mb < 2; mb++) {
        const int r0 = rowBase + wm + mb * 16 + r0l;
        const int r1 = r0 + 8;
        const float d0 = D[r0], d1 = D[r1];
        #pragma unroll
        for (int nb = 0; nb < 4; nb++) {
            const int c = wn + nb * 8 + 2 * krl;
            float2 z0 = *(const float2*)&Z[(size_t)r0 * DIM + c];
            float2 z1 = *(const float2*)&Z[(size_t)r1 * DIM + c];
            float2 h0, h1, zo0, zo1;
            h0.x = d0 * (acc[mb][nb][0] + z0.x);
            h0.y = d0 * (acc[mb][nb][1] + z0.y);
            h1.x = d1 * (acc[mb][nb][2] + z1.x);
            h1.y = d1 * (acc[mb][nb][3] + z1.y);
            zo0.x = d0 * h0.x; zo0.y = d0 * h0.y;
            zo1.x = d1 * h1.x; zo1.y = d1 * h1.y;
            *(float2*)&H [(size_t)r0 * DIM + c] = h0;
            *(float2*)&H [(size_t)r1 * DIM + c] = h1;
            *(float2*)&ZO[(size_t)r0 * DIM + c] = zo0;
            *(float2*)&ZO[(size_t)r1 * DIM + c] = zo1;
        }
    }
}

// ---------------- 4) out = concat(x,h1,h2,h3) @ W^T + b ----------------
__global__ void __launch_bounds__(256)
out_gemm_kernel(const float* __restrict__ x,
                const float* __restrict__ h1,
                const float* __restrict__ h2,
                const float* __restrict__ h3,
                const float* __restrict__ W,
                const float* __restrict__ bias,
                float* __restrict__ out)
{
    __shared__ float catS[16][256];
    __shared__ float Wt[64][65];

    const int tid = threadIdx.x;
    const int rowBase = blockIdx.x * 16;

    const float* srcs[4] = { x, h1, h2, h3 };
    {
        int r = tid >> 4, f4 = tid & 15;
        #pragma unroll
        for (int s = 0; s < 4; s++) {
            float4 v = *(const float4*)&srcs[s][(size_t)(rowBase + r) * DIM + f4 * 4];
            *(float4*)&catS[r][s * 64 + f4 * 4] = v;
        }
    }

    const int o  = tid & 63;
    const int rg = tid >> 6;

    float acc[4];
    {
        float bv = bias[o];
        #pragma unroll
        for (int j = 0; j < 4; j++) acc[j] = bv;
    }

    for (int fc = 0; fc < 4; fc++) {
        __syncthreads();
        #pragma unroll
        for (int u = 0; u < 4; u++) {
            int i  = tid + u * 256;
            int ro = i >> 4;
            int f4 = i & 15;
            float4 v = *(const float4*)&W[(size_t)ro * 256 + fc * 64 + f4 * 4];
            Wt[f4 * 4 + 0][ro] = v.x;
            Wt[f4 * 4 + 1][ro] = v.y;
            Wt[f4 * 4 + 2][ro] = v.z;
            Wt[f4 * 4 + 3][ro] = v.w;
        }
        __syncthreads();
        #pragma unroll
        for (int fl = 0; fl < 64; fl++) {
            float w = Wt[fl][o];
            #pragma unroll
            for (int j = 0; j < 4; j++)
                acc[j] += catS[rg * 4 + j][fc * 64 + fl] * w;
        }
    }

    #pragma unroll
    for (int j = 0; j < 4; j++)
        out[(size_t)(rowBase + rg * 4 + j) * DIM + o] = acc[j];
}

// ---------------- launch ----------------
static float* symAddr(const void* symbol) {
    void* p = nullptr;
    cudaGetSymbolAddress(&p, symbol);
    return (float*)p;
}

extern "C" void kernel_launch(void* const* d_in, const int* in_sizes, int n_in,
                              void* d_out, int out_size) {
    const float* x     = (const float*)d_in[0];
    const float* graph = (const float*)d_in[1];
    const float* W     = (const float*)d_in[2];
    const float* bias  = (const float*)d_in[3];
    float* out = (float*)d_out;

    float* deg = symAddr(g_deg);
    float* zA  = symAddr(g_zA);
    float* zB  = symAddr(g_zB);
    float* h1  = symAddr(g_h1);
    float* h2  = symAddr(g_h2);
    float* h3  = symAddr(g_h3);

    degree_kernel<<<BATCH * NNODES, 256>>>(graph, deg);
    scale_x_kernel<<<(BATCH * NNODES * DIM / 4) / 256, 256>>>(x, deg, zA);

    dim3 gg(NNODES / TM, BATCH);
    prop_mma_kernel<<<gg, THREADS>>>(graph, zA, h1, zB);
    prop_mma_kernel<<<gg, THREADS>>>(graph, zB, h2, zA);
    prop_mma_kernel<<<gg, THREADS>>>(graph, zA, h3, zB);

    out_gemm_kernel<<<(BATCH * NNODES) / 16, 256>>>(x, h1, h2, h3, W, bias, out);
}